// round 1
// baseline (speedup 1.0000x reference)
#include <cuda_runtime.h>

// ---------------------------------------------------------------------------
// HimpNetAlternative: out = scatter_mean( relu(relu(X@W1+b1)@W2+b2), to_index )
// E=320000, C=256, N=10000
//
// Round 0: fp32 tiled SGEMM baseline.
//   k0: zero d_out (sums) + counts
//   k1: histogram of to_index -> counts
//   k2: m1 = relu(X @ W1 + b1)            (scratch in __device__ global)
//   k3: relu(m1 @ W2 + b2) atomically scattered into d_out (sums)
//   k4: finalize: out = cnt>0 ? sum/cnt : 0
// ---------------------------------------------------------------------------

#define BM 128
#define BN 128
#define BK 16
#define TM 8
#define TN 8

static constexpr int E_CONST = 320000;
static constexpr int C_CONST = 256;
static constexpr int N_MAX   = 16384;

// Scratch: intermediate m1 [E, C] (327.68 MB) and per-node counts.
__device__ float g_m1[(size_t)E_CONST * C_CONST];
__device__ int   g_cnt[N_MAX];

// ---------------------------------------------------------------------------

__global__ void zero_kernel(float* __restrict__ out, int n_out,
                            int* __restrict__ cnt, int n_nodes) {
    int i = blockIdx.x * blockDim.x + threadIdx.x;
    if (i < n_out)   out[i] = 0.0f;
    if (i < n_nodes) cnt[i] = 0;
}

__global__ void hist_kernel(const int* __restrict__ to_index, int E,
                            int* __restrict__ cnt) {
    int i = blockIdx.x * blockDim.x + threadIdx.x;
    if (i < E) atomicAdd(&cnt[to_index[i]], 1);
}

// Tiled SGEMM: out[M,N] = relu(A[M,K] @ W[K,N] + bias[N])
// SCATTER=false: store rows to out (stride N).
// SCATTER=true : atomicAdd rows into out[to_index[row]*N + col].
template <bool SCATTER>
__global__ __launch_bounds__(256, 2)
void gemm_relu_kernel(const float* __restrict__ A,
                      const float* __restrict__ W,
                      const float* __restrict__ bias,
                      float* __restrict__ out,
                      const int* __restrict__ to_index,
                      int M, int N, int K) {
    __shared__ float As[BK][BM];   // A tile, transposed
    __shared__ float Bs[BK][BN];   // W tile

    const int tid = threadIdx.x;            // 256 threads
    const int tx  = tid & 15;                // 0..15
    const int ty  = tid >> 4;                // 0..15
    const int block_row = blockIdx.y * BM;
    const int block_col = blockIdx.x * BN;

    float acc[TM][TN];
#pragma unroll
    for (int i = 0; i < TM; i++)
#pragma unroll
        for (int j = 0; j < TN; j++) acc[i][j] = 0.0f;

    for (int kt = 0; kt < K; kt += BK) {
        // Load A tile: BM x BK = 2048 floats = 512 float4 (2 per thread)
#pragma unroll
        for (int l = 0; l < 2; l++) {
            int f   = tid + l * 256;
            int row = f >> 2;              // 0..127
            int kk  = (f & 3) * 4;         // 0,4,8,12
            int gr  = block_row + row;
            if (gr >= M) gr = M - 1;       // clamp (E is a multiple of BM anyway)
            float4 v = *(const float4*)(A + (size_t)gr * K + kt + kk);
            As[kk + 0][row] = v.x;
            As[kk + 1][row] = v.y;
            As[kk + 2][row] = v.z;
            As[kk + 3][row] = v.w;
        }
        // Load W tile: BK x BN = 2048 floats = 512 float4 (2 per thread)
#pragma unroll
        for (int l = 0; l < 2; l++) {
            int f   = tid + l * 256;
            int row = f >> 5;              // 0..15
            int col = (f & 31) * 4;        // 0..124
            *(float4*)(&Bs[row][col]) =
                *(const float4*)(W + (size_t)(kt + row) * N + block_col + col);
        }
        __syncthreads();

#pragma unroll
        for (int k = 0; k < BK; k++) {
            float4 a0 = *(const float4*)(&As[k][ty * TM]);
            float4 a1 = *(const float4*)(&As[k][ty * TM + 4]);
            float4 b0 = *(const float4*)(&Bs[k][tx * TN]);
            float4 b1 = *(const float4*)(&Bs[k][tx * TN + 4]);
            float a[TM] = {a0.x, a0.y, a0.z, a0.w, a1.x, a1.y, a1.z, a1.w};
            float b[TN] = {b0.x, b0.y, b0.z, b0.w, b1.x, b1.y, b1.z, b1.w};
#pragma unroll
            for (int i = 0; i < TM; i++)
#pragma unroll
                for (int j = 0; j < TN; j++)
                    acc[i][j] = fmaf(a[i], b[j], acc[i][j]);
        }
        __syncthreads();
    }

    // Bias for this thread's 8 columns
    float4 bv0 = *(const float4*)(bias + block_col + tx * TN);
    float4 bv1 = *(const float4*)(bias + block_col + tx * TN + 4);
    float bv[TN] = {bv0.x, bv0.y, bv0.z, bv0.w, bv1.x, bv1.y, bv1.z, bv1.w};

#pragma unroll
    for (int i = 0; i < TM; i++) {
        int row = block_row + ty * TM + i;
        if (row >= M) continue;
        float v[TN];
#pragma unroll
        for (int j = 0; j < TN; j++) {
            float t = acc[i][j] + bv[j];
            v[j] = t > 0.0f ? t : 0.0f;
        }
        if (!SCATTER) {
            float* orow = out + (size_t)row * N + block_col + tx * TN;
            *(float4*)(orow)     = make_float4(v[0], v[1], v[2], v[3]);
            *(float4*)(orow + 4) = make_float4(v[4], v[5], v[6], v[7]);
        } else {
            int node = to_index[row];
            float* orow = out + (size_t)node * N + block_col + tx * TN;
#pragma unroll
            for (int j = 0; j < TN; j++) atomicAdd(orow + j, v[j]);
        }
    }
}

__global__ void finalize_kernel(float* __restrict__ out,
                                const int* __restrict__ cnt,
                                int total, int C_log2mask) {
    int i = blockIdx.x * blockDim.x + threadIdx.x;
    if (i >= total) return;
    int node = i >> 8;                 // C == 256
    int c = cnt[node];
    float v = out[i];
    out[i] = (c > 0) ? v / (float)c : 0.0f;
}

// ---------------------------------------------------------------------------

extern "C" void kernel_launch(void* const* d_in, const int* in_sizes, int n_in,
                              void* d_out, int out_size) {
    // metadata order: from_tensor, to_index, [dim_size], W1, b1, W2, b2
    const float* X  = (const float*)d_in[0];
    const int*   ti = (const int*)d_in[1];
    int wi = 2;
    if (n_in >= 7 && in_sizes[2] <= 4) wi = 3;   // dim_size passed as scalar
    const float* W1 = (const float*)d_in[wi];
    const float* b1 = (const float*)d_in[wi + 1];
    const float* W2 = (const float*)d_in[wi + 2];
    const float* b2 = (const float*)d_in[wi + 3];

    const int E = in_sizes[1];          // 320000
    const int C = in_sizes[wi + 1];     // 256
    const int N = out_size / C;         // 10000
    float* out = (float*)d_out;

    float* m1;
    int*   cnt;
    cudaGetSymbolAddress((void**)&m1, g_m1);
    cudaGetSymbolAddress((void**)&cnt, g_cnt);

    // k0: zero sums + counts
    {
        int threads = 256;
        int blocks = (out_size + threads - 1) / threads;   // covers N too (N << out_size)
        zero_kernel<<<blocks, threads>>>(out, out_size, cnt, N);
    }
    // k1: histogram
    hist_kernel<<<(E + 255) / 256, 256>>>(ti, E, cnt);

    // k2: m1 = relu(X @ W1 + b1)
    dim3 grid1(C / BN, (E + BM - 1) / BM);
    gemm_relu_kernel<false><<<grid1, 256>>>(X, W1, b1, m1, nullptr, E, C, C);

    // k3: scatter-add relu(m1 @ W2 + b2)
    gemm_relu_kernel<true><<<grid1, 256>>>(m1, W2, b2, out, ti, E, C, C);

    // k4: mean
    finalize_kernel<<<(out_size + 255) / 256, 256>>>(out, cnt, out_size, C);
}

// round 3
// speedup vs baseline: 3.0960x; 3.0960x over previous
#include <cuda_runtime.h>
#include <cstdint>

// ---------------------------------------------------------------------------
// HimpNetAlternative: out = scatter_mean( relu(relu(X@W1+b1)@W2+b2), to_index )
// E=320000, C=256, N=10000
//
// Round 3: mma.sync.m16n8k8.tf32 (baseline PTX; tcgen05 rejected by the
// harness's compute_103 virtual arch). CTA 128x128, 8 warps @ 32x64,
// 3-stage cp.async, B pre-packed into fragment order (+tf32 pre-convert).
// ---------------------------------------------------------------------------

static constexpr int E_CONST = 320000;
static constexpr int C_CONST = 256;

__device__ float g_m1[(size_t)E_CONST * C_CONST];          // relu(X@W1+b1)
// packed W per layer: [s(32)][nb(2)][f'(16)][lane(32)][i(2)] floats (tf32 bits)
__device__ float g_wpack[2][32 * 2 * 16 * 32 * 2];
__device__ int   g_cnt[16384];

// ------------------------------- helpers ----------------------------------

__device__ __forceinline__ uint32_t smem_u32(const void* p) {
    uint32_t a;
    asm("{ .reg .u64 t; cvta.to.shared.u64 t, %1; cvt.u32.u64 %0, t; }"
        : "=r"(a) : "l"(p));
    return a;
}

__device__ __forceinline__ uint32_t f2tf32(float f) {
    uint32_t u;
    asm("cvt.rna.tf32.f32 %0, %1;" : "=r"(u) : "f"(f));
    return u;
}

__device__ __forceinline__ void mma_tf32(float* d, const uint32_t* a,
                                         const uint32_t* b) {
    asm volatile(
        "mma.sync.aligned.m16n8k8.row.col.f32.tf32.tf32.f32 "
        "{%0,%1,%2,%3}, {%4,%5,%6,%7}, {%8,%9}, {%0,%1,%2,%3};"
        : "+f"(d[0]), "+f"(d[1]), "+f"(d[2]), "+f"(d[3])
        : "r"(a[0]), "r"(a[1]), "r"(a[2]), "r"(a[3]), "r"(b[0]), "r"(b[1]));
}

__device__ __forceinline__ void cpa16(uint32_t s, const float* g) {
    asm volatile("cp.async.cg.shared.global [%0], [%1], 16;" :: "r"(s), "l"(g));
}

// --------------------------------- prep -----------------------------------

__global__ void zero_kernel(float* __restrict__ out, int n_out,
                            int* __restrict__ cnt, int n_nodes) {
    int i = blockIdx.x * blockDim.x + threadIdx.x;
    if (i < n_out)   out[i] = 0.0f;
    if (i < n_nodes) cnt[i] = 0;
}

__global__ void hist_kernel(const int* __restrict__ to_index, int E,
                            int* __restrict__ cnt) {
    int i = blockIdx.x * blockDim.x + threadIdx.x;
    if (i < E) atomicAdd(&cnt[to_index[i]], 1);
}

// Pack W[k][n] (256x256 row-major) into mma B-fragment order + tf32 round.
__global__ void pack_w_kernel(const float* __restrict__ W, float* __restrict__ dst) {
    int o = blockIdx.x * 256 + threadIdx.x;   // 65536
    int i  = o & 1;
    int l  = (o >> 1) & 31;
    int fp = (o >> 6) & 15;
    int nb = (o >> 10) & 1;
    int s  = o >> 11;
    int k = s * 8 + (l & 3) + 4 * i;
    int n = nb * 128 + fp * 8 + (l >> 2);
    dst[o] = __uint_as_float(f2tf32(W[k * 256 + n]));
}

__global__ void finalize_kernel(float* __restrict__ out,
                                const int* __restrict__ cnt, int total) {
    int i = blockIdx.x * blockDim.x + threadIdx.x;
    if (i >= total) return;
    int c = cnt[i >> 8];
    float v = out[i];
    out[i] = (c > 0) ? v / (float)c : 0.0f;
}

// --------------------------------- GEMM -----------------------------------
// smem: As 3 stages * 128*20 floats ; Bs 3 stages * 2048 floats
static constexpr int AS_STAGE = 128 * 20;   // floats (pitch 20: bank-conflict-free)
static constexpr int BS_STAGE = 2048;       // floats
static constexpr int SMEM_FLOATS = 3 * AS_STAGE + 3 * BS_STAGE;
static constexpr size_t SHMEM_BYTES = SMEM_FLOATS * 4;

template <bool SCATTER>
__global__ void __launch_bounds__(256)
mma_mlp_kernel(const float* __restrict__ A, const float* __restrict__ Wp,
               const float* __restrict__ bias, float* __restrict__ out,
               const int* __restrict__ ti) {
    extern __shared__ float smem[];
    float* As = smem;
    float* Bs = smem + 3 * AS_STAGE;
    const uint32_t sA = smem_u32(As);
    const uint32_t sB = smem_u32(Bs);

    const int tid  = threadIdx.x;
    const int lane = tid & 31, wid = tid >> 5;
    const int wm = wid & 3, wn = wid >> 2;
    const int gid = lane >> 2, tig = lane & 3;
    const int nb   = blockIdx.x;               // 0/1: which 128-col half
    const int brow = blockIdx.y * 128;

    const float* Asrc = A + (size_t)brow * 256;
    const float* Bsrc = Wp + nb * 1024;        // (s,nb) block stride = 2048 floats

    float acc[2][8][4];
#pragma unroll
    for (int m = 0; m < 2; m++)
#pragma unroll
        for (int j = 0; j < 8; j++)
#pragma unroll
            for (int q = 0; q < 4; q++) acc[m][j][q] = 0.0f;

    // ---- staging ----
    auto load_chunk = [&](int c, int st) {
#pragma unroll
        for (int i = 0; i < 2; i++) {           // A: 512 float4
            int f = tid + i * 256;
            int m = f >> 2, c4 = f & 3;
            cpa16(sA + (uint32_t)(st * AS_STAGE + m * 20) * 4 + c4 * 16,
                  Asrc + (size_t)m * 256 + c * 16 + c4 * 4);
        }
#pragma unroll
        for (int i = 0; i < 2; i++) {           // B: 512 float4
            int f = tid + i * 256;              // float4 index in stage
            int s01 = f >> 8;
            int rem = f & 255;
            cpa16(sB + (uint32_t)(st * BS_STAGE) * 4 + f * 16,
                  Bsrc + (size_t)(c * 2 + s01) * 2048 + rem * 4);
        }
    };

    // ---- compute one BK=16 chunk (two k8 steps) ----
    auto compute_chunk = [&](int st) {
        const float* as = As + st * AS_STAGE + wm * 32 * 20;
        const float* bs = Bs + st * BS_STAGE + wn * 8 * 64;
#pragma unroll
        for (int sl = 0; sl < 2; sl++) {
            uint32_t a[2][4];
#pragma unroll
            for (int mf = 0; mf < 2; mf++) {
                int r = mf * 16 + gid, col = sl * 8 + tig;
                a[mf][0] = f2tf32(as[r * 20 + col]);
                a[mf][1] = f2tf32(as[(r + 8) * 20 + col]);
                a[mf][2] = f2tf32(as[r * 20 + col + 4]);
                a[mf][3] = f2tf32(as[(r + 8) * 20 + col + 4]);
            }
            uint32_t b[8][2];
#pragma unroll
            for (int j = 0; j < 8; j++) {
                float2 v = *(const float2*)(bs + sl * 1024 + j * 64 + lane * 2);
                b[j][0] = __float_as_uint(v.x);
                b[j][1] = __float_as_uint(v.y);
            }
#pragma unroll
            for (int mf = 0; mf < 2; mf++)
#pragma unroll
                for (int j = 0; j < 8; j++)
                    mma_tf32(acc[mf][j], a[mf], b[j]);
        }
    };

    // ---- 3-stage pipeline over 16 chunks ----
    load_chunk(0, 0); asm volatile("cp.async.commit_group;" ::: "memory");
    load_chunk(1, 1); asm volatile("cp.async.commit_group;" ::: "memory");
    load_chunk(2, 2); asm volatile("cp.async.commit_group;" ::: "memory");

    for (int c = 0; c < 16; c++) {
        const int st = c % 3;
        asm volatile("cp.async.wait_group 2;" ::: "memory");
        __syncthreads();
        compute_chunk(st);
        __syncthreads();
        if (c + 3 < 16) load_chunk(c + 3, st);
        asm volatile("cp.async.commit_group;" ::: "memory");
    }

    // ---- epilogue ----
    const int colb = nb * 128 + wn * 64;
    float2 bv[8];
#pragma unroll
    for (int j = 0; j < 8; j++)
        bv[j] = *(const float2*)(bias + colb + j * 8 + tig * 2);

#pragma unroll
    for (int mf = 0; mf < 2; mf++) {
        const int r0 = brow + wm * 32 + mf * 16 + gid;
        const int r1 = r0 + 8;
        if (!SCATTER) {
            float* p0 = out + (size_t)r0 * 256 + colb + tig * 2;
            float* p1 = out + (size_t)r1 * 256 + colb + tig * 2;
#pragma unroll
            for (int j = 0; j < 8; j++) {
                float2 v0, v1;
                v0.x = fmaxf(acc[mf][j][0] + bv[j].x, 0.f);
                v0.y = fmaxf(acc[mf][j][1] + bv[j].y, 0.f);
                v1.x = fmaxf(acc[mf][j][2] + bv[j].x, 0.f);
                v1.y = fmaxf(acc[mf][j][3] + bv[j].y, 0.f);
                *(float2*)(p0 + j * 8) = v0;
                *(float2*)(p1 + j * 8) = v1;
            }
        } else {
            const int n0 = ti[r0], n1 = ti[r1];
            float* p0 = out + (size_t)n0 * 256 + colb + tig * 2;
            float* p1 = out + (size_t)n1 * 256 + colb + tig * 2;
#pragma unroll
            for (int j = 0; j < 8; j++) {
                float v;
                v = acc[mf][j][0] + bv[j].x; if (v > 0.f) atomicAdd(p0 + j * 8,     v);
                v = acc[mf][j][1] + bv[j].y; if (v > 0.f) atomicAdd(p0 + j * 8 + 1, v);
                v = acc[mf][j][2] + bv[j].x; if (v > 0.f) atomicAdd(p1 + j * 8,     v);
                v = acc[mf][j][3] + bv[j].y; if (v > 0.f) atomicAdd(p1 + j * 8 + 1, v);
            }
        }
    }
}

// ------------------------------ kernel_launch -----------------------------

extern "C" void kernel_launch(void* const* d_in, const int* in_sizes, int n_in,
                              void* d_out, int out_size) {
    const float* X  = (const float*)d_in[0];
    const int*   ti = (const int*)d_in[1];
    int wi = 2;
    if (n_in >= 7 && in_sizes[2] <= 4) wi = 3;
    const float* W1 = (const float*)d_in[wi];
    const float* b1 = (const float*)d_in[wi + 1];
    const float* W2 = (const float*)d_in[wi + 2];
    const float* b2 = (const float*)d_in[wi + 3];

    const int E = in_sizes[1];        // 320000
    const int N = out_size / 256;     // 10000
    float* out = (float*)d_out;

    float* m1;  float* wp0;  int* cnt;
    cudaGetSymbolAddress((void**)&m1, g_m1);
    cudaGetSymbolAddress((void**)&cnt, g_cnt);
    cudaGetSymbolAddress((void**)&wp0, g_wpack);
    float* wp1 = wp0 + 32 * 2 * 16 * 32 * 2;

    cudaFuncSetAttribute(mma_mlp_kernel<false>,
                         cudaFuncAttributeMaxDynamicSharedMemorySize, (int)SHMEM_BYTES);
    cudaFuncSetAttribute(mma_mlp_kernel<true>,
                         cudaFuncAttributeMaxDynamicSharedMemorySize, (int)SHMEM_BYTES);

    // prep
    pack_w_kernel<<<256, 256>>>(W1, wp0);
    pack_w_kernel<<<256, 256>>>(W2, wp1);
    zero_kernel<<<(out_size + 255) / 256, 256>>>(out, out_size, cnt, N);
    hist_kernel<<<(E + 255) / 256, 256>>>(ti, E, cnt);

    dim3 grid(2, E / 128);   // (2, 2500)
    mma_mlp_kernel<false><<<grid, 256, SHMEM_BYTES>>>(X,  wp0, b1, m1,  nullptr);
    mma_mlp_kernel<true ><<<grid, 256, SHMEM_BYTES>>>(m1, wp1, b2, out, ti);
    finalize_kernel<<<(out_size + 255) / 256, 256>>>(out, cnt, out_size);
}

// round 4
// speedup vs baseline: 4.3841x; 1.4160x over previous
#include <cuda_runtime.h>
#include <cuda_fp16.h>
#include <cstdint>

// ---------------------------------------------------------------------------
// HimpNetAlternative: out = scatter_mean( relu(relu(X@W1+b1)@W2+b2), to_index )
// E=320000, C=256, N=10000
//
// Round 4: fp16 HMMA (mma.sync.m16n8k16.f16 with fp32 accum).
//   - X pre-converted to fp16 once; m1 kept in fp16 (halves its traffic).
//   - A-fragments via ldmatrix.x4 from pitch-24 smem (conflict-free).
//   - B pre-packed into fragment order: 4x LDS.128 per warp per k16 chunk.
//   - GEMM2 epilogue: zero-skipped fp32 atomic scatter; finalize divides.
// ---------------------------------------------------------------------------

static constexpr int E_CONST = 320000;

__device__ __half g_xh[(size_t)E_CONST * 256];   // fp16 copy of X
__device__ __half g_m1[(size_t)E_CONST * 256];   // fp16 relu(X@W1+b1)
__device__ __half g_wpack[2][65536];             // W fragments, fp16
__device__ int    g_cnt[16384];

// ------------------------------- helpers ----------------------------------

__device__ __forceinline__ uint32_t smem_u32(const void* p) {
    uint32_t a;
    asm("{ .reg .u64 t; cvta.to.shared.u64 t, %1; cvt.u32.u64 %0, t; }"
        : "=r"(a) : "l"(p));
    return a;
}

__device__ __forceinline__ void cpa16(uint32_t s, const void* g) {
    asm volatile("cp.async.cg.shared.global [%0], [%1], 16;" :: "r"(s), "l"(g));
}

__device__ __forceinline__ void ldmx4(uint32_t* r, uint32_t addr) {
    asm volatile("ldmatrix.sync.aligned.m8n8.x4.shared.b16 {%0,%1,%2,%3}, [%4];"
                 : "=r"(r[0]), "=r"(r[1]), "=r"(r[2]), "=r"(r[3]) : "r"(addr));
}

__device__ __forceinline__ void mma_f16(float* d, const uint32_t* a,
                                        const uint32_t* b) {
    asm volatile(
        "mma.sync.aligned.m16n8k16.row.col.f32.f16.f16.f32 "
        "{%0,%1,%2,%3}, {%4,%5,%6,%7}, {%8,%9}, {%0,%1,%2,%3};"
        : "+f"(d[0]), "+f"(d[1]), "+f"(d[2]), "+f"(d[3])
        : "r"(a[0]), "r"(a[1]), "r"(a[2]), "r"(a[3]), "r"(b[0]), "r"(b[1]));
}

// --------------------------------- prep -----------------------------------

__global__ void cvt_kernel(const float* __restrict__ X, __half* __restrict__ Xh) {
    int i = blockIdx.x * blockDim.x + threadIdx.x;     // one per 8 elements
    float4 a = ((const float4*)X)[i * 2];
    float4 b = ((const float4*)X)[i * 2 + 1];
    __half2 h[4];
    h[0] = __floats2half2_rn(a.x, a.y);
    h[1] = __floats2half2_rn(a.z, a.w);
    h[2] = __floats2half2_rn(b.x, b.y);
    h[3] = __floats2half2_rn(b.z, b.w);
    ((uint2*)Xh)[i * 2]     = make_uint2(*(uint32_t*)&h[0], *(uint32_t*)&h[1]);
    ((uint2*)Xh)[i * 2 + 1] = make_uint2(*(uint32_t*)&h[2], *(uint32_t*)&h[3]);
}

__global__ void zero_kernel(float* __restrict__ out, int n_out,
                            int* __restrict__ cnt, int n_nodes) {
    int i = blockIdx.x * blockDim.x + threadIdx.x;
    if (i < n_out)   out[i] = 0.0f;
    if (i < n_nodes) cnt[i] = 0;
}

__global__ void hist_kernel(const int* __restrict__ to_index, int E,
                            int* __restrict__ cnt) {
    int i = blockIdx.x * blockDim.x + threadIdx.x;
    if (i < E) atomicAdd(&cnt[to_index[i]], 1);
}

// Pack W[k][n] (256x256 row-major, fp32) into fp16 mma-B fragment order:
// [s(16)][nb(2)][f2(8)][lane(32)][fp(2)][i(4)]  (i: b0lo,b0hi,b1lo,b1hi)
__global__ void pack_w_kernel(const float* __restrict__ W, __half* __restrict__ dst) {
    int o = blockIdx.x * 256 + threadIdx.x;      // 65536 halves
    int i    = o & 3;
    int fp   = (o >> 2) & 1;
    int lane = (o >> 3) & 31;
    int f2   = (o >> 8) & 7;
    int nb   = (o >> 11) & 1;
    int s    = o >> 12;
    int f = f2 * 2 + fp;
    int n = nb * 128 + f * 8 + (lane >> 2);
    int k = s * 16 + (lane & 3) * 2 + (i & 1) + (i >> 1) * 8;
    dst[o] = __float2half_rn(W[k * 256 + n]);
}

__global__ void finalize_kernel(float* __restrict__ out,
                                const int* __restrict__ cnt, int total) {
    int i = blockIdx.x * blockDim.x + threadIdx.x;
    if (i >= total) return;
    int c = cnt[i >> 8];
    float v = out[i];
    out[i] = (c > 0) ? v / (float)c : 0.0f;
}

// --------------------------------- GEMM -----------------------------------
// CTA 128x128, 8 warps (4M x 2N), warp tile 32x64, K-chunks of 16, 3 stages.
static constexpr int AS_PITCH = 24;              // halves; conflict-free ldmatrix
static constexpr int AS_STAGE = 128 * AS_PITCH;  // 3072 halves
static constexpr int BS_STAGE = 2048;            // halves

template <bool SCATTER>
__global__ void __launch_bounds__(256)
mma_mlp_kernel(const __half* __restrict__ A, const __half* __restrict__ Wp,
               const float* __restrict__ bias, void* __restrict__ out_raw,
               const int* __restrict__ ti) {
    __shared__ __half As[3 * AS_STAGE];
    __shared__ __half Bs[3 * BS_STAGE];

    const int tid  = threadIdx.x;
    const int lane = tid & 31, wid = tid >> 5;
    const int wm = wid & 3, wn = wid >> 2;
    const int gid = lane >> 2, tig = lane & 3;
    const int nb   = blockIdx.x;                // 128-col half
    const int brow = blockIdx.y * 128;

    const __half* Asrc = A + (size_t)brow * 256;
    const __half* Bsrc = Wp + nb * 2048;        // s-stride = 4096 halves

    float acc[2][8][4];
#pragma unroll
    for (int m = 0; m < 2; m++)
#pragma unroll
        for (int j = 0; j < 8; j++)
#pragma unroll
            for (int q = 0; q < 4; q++) acc[m][j][q] = 0.0f;

    // per-thread load slots (one cp.async each for A and B per chunk)
    const int arow = tid >> 1, ahf = tid & 1;

    auto load_chunk = [&](int c, int st) {
        cpa16(smem_u32(&As[st * AS_STAGE + arow * AS_PITCH + ahf * 8]),
              Asrc + (size_t)arow * 256 + c * 16 + ahf * 8);
        cpa16(smem_u32(&Bs[st * BS_STAGE + tid * 8]),
              Bsrc + (size_t)c * 4096 + tid * 8);
    };

    auto compute_chunk = [&](int st) {
        uint32_t a[2][4];
        const uint32_t abase = smem_u32(&As[st * AS_STAGE + wm * 32 * AS_PITCH]);
#pragma unroll
        for (int mf = 0; mf < 2; mf++)
            ldmx4(a[mf], abase +
                  (uint32_t)(((mf * 16 + (lane & 15)) * AS_PITCH + (lane >> 4) * 8) * 2));
        uint32_t b[8][2];
        const __half* bs = &Bs[st * BS_STAGE + wn * 4 * 256];
#pragma unroll
        for (int j2 = 0; j2 < 4; j2++) {
            uint4 v = *(const uint4*)(bs + j2 * 256 + lane * 8);
            b[j2 * 2][0] = v.x; b[j2 * 2][1] = v.y;
            b[j2 * 2 + 1][0] = v.z; b[j2 * 2 + 1][1] = v.w;
        }
#pragma unroll
        for (int mf = 0; mf < 2; mf++)
#pragma unroll
            for (int j = 0; j < 8; j++)
                mma_f16(acc[mf][j], a[mf], b[j]);
    };

    // ---- 3-stage pipeline over 16 chunks ----
    load_chunk(0, 0); asm volatile("cp.async.commit_group;" ::: "memory");
    load_chunk(1, 1); asm volatile("cp.async.commit_group;" ::: "memory");
    load_chunk(2, 2); asm volatile("cp.async.commit_group;" ::: "memory");

    for (int c = 0; c < 16; c++) {
        const int st = c % 3;
        asm volatile("cp.async.wait_group 2;" ::: "memory");
        __syncthreads();
        compute_chunk(st);
        __syncthreads();
        if (c + 3 < 16) load_chunk(c + 3, st);
        asm volatile("cp.async.commit_group;" ::: "memory");
    }

    // ---- epilogue ----
    const int colb = nb * 128 + wn * 64;
    float2 bv[8];
#pragma unroll
    for (int j = 0; j < 8; j++)
        bv[j] = *(const float2*)(bias + colb + j * 8 + tig * 2);

#pragma unroll
    for (int mf = 0; mf < 2; mf++) {
        const int r0 = brow + wm * 32 + mf * 16 + gid;
        const int r1 = r0 + 8;
        if (!SCATTER) {
            __half* m1o = (__half*)out_raw;
            __half* p0 = m1o + (size_t)r0 * 256 + colb + tig * 2;
            __half* p1 = m1o + (size_t)r1 * 256 + colb + tig * 2;
#pragma unroll
            for (int j = 0; j < 8; j++) {
                *(__half2*)(p0 + j * 8) = __floats2half2_rn(
                    fmaxf(acc[mf][j][0] + bv[j].x, 0.f),
                    fmaxf(acc[mf][j][1] + bv[j].y, 0.f));
                *(__half2*)(p1 + j * 8) = __floats2half2_rn(
                    fmaxf(acc[mf][j][2] + bv[j].x, 0.f),
                    fmaxf(acc[mf][j][3] + bv[j].y, 0.f));
            }
        } else {
            float* outf = (float*)out_raw;
            const int n0 = ti[r0], n1 = ti[r1];
            float* p0 = outf + (size_t)n0 * 256 + colb + tig * 2;
            float* p1 = outf + (size_t)n1 * 256 + colb + tig * 2;
#pragma unroll
            for (int j = 0; j < 8; j++) {
                float v;
                v = acc[mf][j][0] + bv[j].x; if (v > 0.f) atomicAdd(p0 + j * 8,     v);
                v = acc[mf][j][1] + bv[j].y; if (v > 0.f) atomicAdd(p0 + j * 8 + 1, v);
                v = acc[mf][j][2] + bv[j].x; if (v > 0.f) atomicAdd(p1 + j * 8,     v);
                v = acc[mf][j][3] + bv[j].y; if (v > 0.f) atomicAdd(p1 + j * 8 + 1, v);
            }
        }
    }
}

// ------------------------------ kernel_launch -----------------------------

extern "C" void kernel_launch(void* const* d_in, const int* in_sizes, int n_in,
                              void* d_out, int out_size) {
    const float* X  = (const float*)d_in[0];
    const int*   ti = (const int*)d_in[1];
    int wi = 2;
    if (n_in >= 7 && in_sizes[2] <= 4) wi = 3;
    const float* W1 = (const float*)d_in[wi];
    const float* b1 = (const float*)d_in[wi + 1];
    const float* W2 = (const float*)d_in[wi + 2];
    const float* b2 = (const float*)d_in[wi + 3];

    const int E = in_sizes[1];        // 320000
    const int N = out_size / 256;     // 10000
    float* out = (float*)d_out;

    __half* xh;  __half* m1;  __half* wp0;  int* cnt;
    cudaGetSymbolAddress((void**)&xh,  g_xh);
    cudaGetSymbolAddress((void**)&m1,  g_m1);
    cudaGetSymbolAddress((void**)&wp0, g_wpack);
    cudaGetSymbolAddress((void**)&cnt, g_cnt);
    __half* wp1 = wp0 + 65536;

    // prep
    cvt_kernel<<<(E * 256 / 8 + 255) / 256, 256>>>(X, xh);
    pack_w_kernel<<<256, 256>>>(W1, wp0);
    pack_w_kernel<<<256, 256>>>(W2, wp1);
    zero_kernel<<<(out_size + 255) / 256, 256>>>(out, out_size, cnt, N);
    hist_kernel<<<(E + 255) / 256, 256>>>(ti, E, cnt);

    dim3 grid(2, E / 128);   // (2, 2500)
    mma_mlp_kernel<false><<<grid, 256>>>(xh, wp0, b1, (void*)m1, nullptr);
    mma_mlp_kernel<true ><<<grid, 256>>>(m1, wp1, b2, (void*)out, ti);
    finalize_kernel<<<(out_size + 255) / 256, 256>>>(out, cnt, out_size);
}

// round 5
// speedup vs baseline: 5.0718x; 1.1569x over previous
#include <cuda_runtime.h>
#include <cuda_fp16.h>
#include <cstdint>

// ---------------------------------------------------------------------------
// HimpNetAlternative: out = scatter_mean( relu(relu(X@W1+b1)@W2+b2), to_index )
// E=320000, C=256, N=10000
//
// Round 5: single fused kernel. Per CTA (128 rows):
//   phase 1: acc = X(fp32, cp.async, in-reg cvt) @ W1pack -> relu -> fp16 smem tile
//   phase 2: smem tile (ldmatrix) @ W2pack -> relu -> zero-skipped atomic scatter
// One __syncthreads per K-chunk; exact tail wait_group constants.
// ---------------------------------------------------------------------------

__device__ __half g_wpack[2][65536];   // W fragments, fp16
__device__ int    g_cnt[16384];

// ------------------------------- helpers ----------------------------------

__device__ __forceinline__ uint32_t smem_u32(const void* p) {
    uint32_t a;
    asm("{ .reg .u64 t; cvta.to.shared.u64 t, %1; cvt.u32.u64 %0, t; }"
        : "=r"(a) : "l"(p));
    return a;
}

__device__ __forceinline__ void cpa16(uint32_t s, const void* g) {
    asm volatile("cp.async.cg.shared.global [%0], [%1], 16;" :: "r"(s), "l"(g));
}

__device__ __forceinline__ void ldmx4(uint32_t* r, uint32_t addr) {
    asm volatile("ldmatrix.sync.aligned.m8n8.x4.shared.b16 {%0,%1,%2,%3}, [%4];"
                 : "=r"(r[0]), "=r"(r[1]), "=r"(r[2]), "=r"(r[3]) : "r"(addr));
}

__device__ __forceinline__ void mma_f16(float* d, const uint32_t* a,
                                        const uint32_t* b) {
    asm volatile(
        "mma.sync.aligned.m16n8k16.row.col.f32.f16.f16.f32 "
        "{%0,%1,%2,%3}, {%4,%5,%6,%7}, {%8,%9}, {%0,%1,%2,%3};"
        : "+f"(d[0]), "+f"(d[1]), "+f"(d[2]), "+f"(d[3])
        : "r"(a[0]), "r"(a[1]), "r"(a[2]), "r"(a[3]), "r"(b[0]), "r"(b[1]));
}

__device__ __forceinline__ uint32_t h2(float x, float y) {
    __half2 h = __floats2half2_rn(x, y);
    return *(uint32_t*)&h;
}

// --------------------------------- prep -----------------------------------

__global__ void zero_kernel(float4* __restrict__ out, int n4,
                            int* __restrict__ cnt, int n_nodes) {
    int i = blockIdx.x * blockDim.x + threadIdx.x;
    if (i < n4)      out[i] = make_float4(0.f, 0.f, 0.f, 0.f);
    if (i < n_nodes) cnt[i] = 0;
}

__global__ void hist_kernel(const int* __restrict__ to_index, int E,
                            int* __restrict__ cnt) {
    int i = blockIdx.x * blockDim.x + threadIdx.x;
    if (i < E) atomicAdd(&cnt[to_index[i]], 1);
}

// Pack W[k][n] (256x256 row-major, fp32) into fp16 mma-B fragment order:
// [s(16)][nb(2)][f2(8)][lane(32)][fp(2)][i(4)]
__global__ void pack_w_kernel(const float* __restrict__ W, __half* __restrict__ dst) {
    int o = blockIdx.x * 256 + threadIdx.x;      // 65536 halves
    int i    = o & 3;
    int fp   = (o >> 2) & 1;
    int lane = (o >> 3) & 31;
    int f2   = (o >> 8) & 7;
    int nb   = (o >> 11) & 1;
    int s    = o >> 12;
    int f = f2 * 2 + fp;
    int n = nb * 128 + f * 8 + (lane >> 2);
    int k = s * 16 + (lane & 3) * 2 + (i & 1) + (i >> 1) * 8;
    dst[o] = __float2half_rn(W[k * 256 + n]);
}

__global__ void finalize_kernel(float* __restrict__ out,
                                const int* __restrict__ cnt, int total) {
    int i = blockIdx.x * blockDim.x + threadIdx.x;
    if (i >= total) return;
    int c = cnt[i >> 8];
    float v = out[i];
    out[i] = (c > 0) ? v / (float)c : 0.0f;
}

// ------------------------------ fused kernel -------------------------------
// smem: Af (fp32 X tiles, 3 stages, pitch 24)   3*12288 B
//       Bs (W fragments, 3 stages, 4096 halves) 3*8192 B
//       M1 (fp16 tile, 128 x pitch 264)         67584 B
static constexpr int AF_PITCH = 24;                   // floats
static constexpr int AF_STAGE = 128 * AF_PITCH;       // floats
static constexpr int BS_STAGE = 4096;                 // halves
static constexpr int M1_PITCH = 264;                  // halves
static constexpr size_t SHMEM_BYTES =
    3 * AF_STAGE * 4 + 3 * BS_STAGE * 2 + 128 * M1_PITCH * 2;   // 129024

__global__ void __launch_bounds__(256)
fused_mlp_kernel(const float* __restrict__ X,
                 const __half* __restrict__ Wp1, const __half* __restrict__ Wp2,
                 const float* __restrict__ b1, const float* __restrict__ b2,
                 float* __restrict__ out, const int* __restrict__ ti) {
    extern __shared__ float smem[];
    float*  Af  = smem;
    __half* Bs  = (__half*)(smem + 3 * AF_STAGE);
    __half* M1  = Bs + 3 * BS_STAGE;

    const int tid  = threadIdx.x;
    const int lane = tid & 31, wid = tid >> 5;
    const int wm = wid & 3, wn = wid >> 2;       // 4M x 2N warps
    const int gid = lane >> 2, tig = lane & 3;
    const int brow = blockIdx.x * 128;

    const float* Asrc = X + (size_t)brow * 256;

    float acc[2][16][4];
#pragma unroll
    for (int m = 0; m < 2; m++)
#pragma unroll
        for (int j = 0; j < 16; j++)
#pragma unroll
            for (int q = 0; q < 4; q++) acc[m][j][q] = 0.0f;

    // --- loaders -----------------------------------------------------------
    const int arow = tid >> 1, ac4 = (tid & 1) * 2;      // A: 2 float4 / thread

    auto loadA = [&](int c, int st) {
#pragma unroll
        for (int i = 0; i < 2; i++) {
            int r = arow, c4 = ac4 + i;
            cpa16(smem_u32(&Af[st * AF_STAGE + r * AF_PITCH + c4 * 4]),
                  Asrc + (size_t)r * 256 + c * 16 + c4 * 4);
        }
    };
    auto loadB = [&](const __half* Wp, int c, int st) {
#pragma unroll
        for (int i = 0; i < 2; i++) {
            int f = tid + i * 256;
            cpa16(smem_u32(&Bs[st * BS_STAGE + f * 8]),
                  Wp + (size_t)c * 4096 + f * 8);
        }
    };

    auto loadBfrags = [&](int st, uint32_t (*b)[2]) {
        const __half* bs = &Bs[st * BS_STAGE + wn * 2048];
#pragma unroll
        for (int j2 = 0; j2 < 8; j2++) {
            uint4 v = *(const uint4*)(bs + j2 * 256 + lane * 8);
            b[j2 * 2][0] = v.x;     b[j2 * 2][1] = v.y;
            b[j2 * 2 + 1][0] = v.z; b[j2 * 2 + 1][1] = v.w;
        }
    };

    // ================= phase 1: acc = X @ W1 =================
    loadA(0, 0); loadB(Wp1, 0, 0);
    asm volatile("cp.async.commit_group;" ::: "memory");
    loadA(1, 1); loadB(Wp1, 1, 1);
    asm volatile("cp.async.commit_group;" ::: "memory");

    for (int c = 0; c < 16; c++) {
        const int st = c % 3;
        if (c < 15) asm volatile("cp.async.wait_group 1;" ::: "memory");
        else        asm volatile("cp.async.wait_group 0;" ::: "memory");
        __syncthreads();
        if (c + 2 < 16) {                       // load into stage (c-1)%3
            const int ls = (c + 2) % 3;
            loadA(c + 2, ls); loadB(Wp1, c + 2, ls);
            asm volatile("cp.async.commit_group;" ::: "memory");
        }
        // A fragments: fp32 smem -> half2 registers
        const float* as = Af + st * AF_STAGE + wm * 32 * AF_PITCH;
        uint32_t a[2][4];
#pragma unroll
        for (int mf = 0; mf < 2; mf++) {
            const float* ar = as + (mf * 16 + gid) * AF_PITCH + tig * 2;
            float2 v0 = *(const float2*)(ar);
            float2 v1 = *(const float2*)(ar + 8 * AF_PITCH);
            float2 v2 = *(const float2*)(ar + 8);
            float2 v3 = *(const float2*)(ar + 8 * AF_PITCH + 8);
            a[mf][0] = h2(v0.x, v0.y);
            a[mf][1] = h2(v1.x, v1.y);
            a[mf][2] = h2(v2.x, v2.y);
            a[mf][3] = h2(v3.x, v3.y);
        }
        uint32_t b[16][2];
        loadBfrags(st, b);
#pragma unroll
        for (int mf = 0; mf < 2; mf++)
#pragma unroll
            for (int j = 0; j < 16; j++)
                mma_f16(acc[mf][j], a[mf], b[j]);
    }

    // ---- phase 1 epilogue: relu(acc + b1) -> fp16 M1 tile ----
#pragma unroll
    for (int mf = 0; mf < 2; mf++) {
        const int r0 = wm * 32 + mf * 16 + gid, r1 = r0 + 8;
#pragma unroll
        for (int j = 0; j < 16; j++) {
            const int col = wn * 128 + j * 8 + tig * 2;
            float2 bv = *(const float2*)(b1 + col);
            *(uint32_t*)&M1[r0 * M1_PITCH + col] =
                h2(fmaxf(acc[mf][j][0] + bv.x, 0.f),
                   fmaxf(acc[mf][j][1] + bv.y, 0.f));
            *(uint32_t*)&M1[r1 * M1_PITCH + col] =
                h2(fmaxf(acc[mf][j][2] + bv.x, 0.f),
                   fmaxf(acc[mf][j][3] + bv.y, 0.f));
        }
    }

#pragma unroll
    for (int m = 0; m < 2; m++)
#pragma unroll
        for (int j = 0; j < 16; j++)
#pragma unroll
            for (int q = 0; q < 4; q++) acc[m][j][q] = 0.0f;

    // ================= phase 2: M1 @ W2, atomic scatter =================
    loadB(Wp2, 0, 0);
    asm volatile("cp.async.commit_group;" ::: "memory");
    loadB(Wp2, 1, 1);
    asm volatile("cp.async.commit_group;" ::: "memory");

    const uint32_t m1base = smem_u32(
        &M1[(wm * 32 + (lane & 15)) * M1_PITCH + (lane >> 4) * 8]);

    for (int c = 0; c < 16; c++) {
        const int st = c % 3;
        if (c < 15) asm volatile("cp.async.wait_group 1;" ::: "memory");
        else        asm volatile("cp.async.wait_group 0;" ::: "memory");
        __syncthreads();   // iter 0: also makes M1 visible to all warps
        if (c + 2 < 16) {
            const int ls = (c + 2) % 3;
            loadB(Wp2, c + 2, ls);
            asm volatile("cp.async.commit_group;" ::: "memory");
        }
        uint32_t a[2][4];
#pragma unroll
        for (int mf = 0; mf < 2; mf++)
            ldmx4(a[mf], m1base + (uint32_t)((mf * 16 * M1_PITCH + c * 16) * 2));
        uint32_t b[16][2];
        loadBfrags(st, b);
#pragma unroll
        for (int mf = 0; mf < 2; mf++)
#pragma unroll
            for (int j = 0; j < 16; j++)
                mma_f16(acc[mf][j], a[mf], b[j]);
    }

    // ---- phase 2 epilogue: relu(acc + b2), zero-skipped atomic scatter ----
#pragma unroll
    for (int mf = 0; mf < 2; mf++) {
        const int r0 = brow + wm * 32 + mf * 16 + gid, r1 = r0 + 8;
        const int n0 = ti[r0], n1 = ti[r1];
        float* p0 = out + (size_t)n0 * 256 + wn * 128 + tig * 2;
        float* p1 = out + (size_t)n1 * 256 + wn * 128 + tig * 2;
#pragma unroll
        for (int j = 0; j < 16; j++) {
            const int col = wn * 128 + j * 8 + tig * 2;
            float2 bv = *(const float2*)(b2 + col);
            float v;
            v = acc[mf][j][0] + bv.x; if (v > 0.f) atomicAdd(p0 + j * 8,     v);
            v = acc[mf][j][1] + bv.y; if (v > 0.f) atomicAdd(p0 + j * 8 + 1, v);
            v = acc[mf][j][2] + bv.x; if (v > 0.f) atomicAdd(p1 + j * 8,     v);
            v = acc[mf][j][3] + bv.y; if (v > 0.f) atomicAdd(p1 + j * 8 + 1, v);
        }
    }
}

// ------------------------------ kernel_launch -----------------------------

extern "C" void kernel_launch(void* const* d_in, const int* in_sizes, int n_in,
                              void* d_out, int out_size) {
    const float* X  = (const float*)d_in[0];
    const int*   ti = (const int*)d_in[1];
    int wi = 2;
    if (n_in >= 7 && in_sizes[2] <= 4) wi = 3;
    const float* W1 = (const float*)d_in[wi];
    const float* b1 = (const float*)d_in[wi + 1];
    const float* W2 = (const float*)d_in[wi + 2];
    const float* b2 = (const float*)d_in[wi + 3];

    const int E = in_sizes[1];        // 320000
    const int N = out_size / 256;     // 10000
    float* out = (float*)d_out;

    __half* wp0;  int* cnt;
    cudaGetSymbolAddress((void**)&wp0, g_wpack);
    cudaGetSymbolAddress((void**)&cnt, g_cnt);
    __half* wp1 = wp0 + 65536;

    cudaFuncSetAttribute(fused_mlp_kernel,
                         cudaFuncAttributeMaxDynamicSharedMemorySize,
                         (int)SHMEM_BYTES);

    pack_w_kernel<<<256, 256>>>(W1, wp0);
    pack_w_kernel<<<256, 256>>>(W2, wp1);
    zero_kernel<<<(out_size / 4 + 255) / 256, 256>>>((float4*)out, out_size / 4,
                                                     cnt, N);
    hist_kernel<<<(E + 255) / 256, 256>>>(ti, E, cnt);

    fused_mlp_kernel<<<E / 128, 256, SHMEM_BYTES>>>(X, wp0, wp1, b1, b2, out, ti);
    finalize_kernel<<<(out_size + 255) / 256, 256>>>(out, cnt, out_size);
}